// round 4
// baseline (speedup 1.0000x reference)
#include <cuda_runtime.h>
#include <cstdint>

#define N_NODES 100000
#define N_EDGES 1000000
#define IN_CH   32
#define EDGE_CH 16
#define OUT_CH  32
#define D_MID   56

typedef unsigned long long u64;

static __device__ int   g_is64;
static __device__ __align__(16) float g_XR[N_NODES * D_MID];  // x @ W1[0:32]  + b1
static __device__ __align__(16) float g_XC[N_NODES * D_MID];  // x @ W1[32:64]

// ---- packed f32x2 helpers ---------------------------------------------------
__device__ __forceinline__ u64 pk2(float a, float b) {
    u64 r; asm("mov.b64 %0, {%1,%2};" : "=l"(r) : "f"(a), "f"(b)); return r;
}
__device__ __forceinline__ void upk2(float& a, float& b, u64 v) {
    asm("mov.b64 {%0,%1}, %2;" : "=f"(a), "=f"(b) : "l"(v));
}
#define FMA2(d, a, b, c) asm("fma.rn.f32x2 %0, %1, %2, %3;" : "=l"(d) : "l"(a), "l"(b), "l"(c))
#define MUL2(d, a, b)    asm("mul.rn.f32x2 %0, %1, %2;"     : "=l"(d) : "l"(a), "l"(b))
#define ADD2(d, a, b)    asm("add.rn.f32x2 %0, %1, %2;"     : "=l"(d) : "l"(a), "l"(b))

// ---------------------------------------------------------------------------
// K0: init output to -inf + (block 0) detect int64 vs int32 edge_index
// ---------------------------------------------------------------------------
__global__ void k_pre(const unsigned int* __restrict__ w, unsigned int* __restrict__ out) {
    if (blockIdx.x == 0) {
        __shared__ int bad;
        if (threadIdx.x == 0) bad = 0;
        __syncthreads();
        for (int i = threadIdx.x; i < 4096; i += blockDim.x)
            if (w[2 * i + 1] != 0u) bad = 1;   // benign race
        __syncthreads();
        if (threadIdx.x == 0) g_is64 = !bad;
    }
    int stride = gridDim.x * blockDim.x;
    for (int i = blockIdx.x * blockDim.x + threadIdx.x; i < N_NODES * OUT_CH; i += stride)
        out[i] = 0xFF800000u;  // -inf
}

// ---------------------------------------------------------------------------
// K1: per-node precompute, 2 nodes per thread (weights LDS amortized)
// ---------------------------------------------------------------------------
__global__ void __launch_bounds__(128, 2) k_node(const float* __restrict__ x,
                                                 const float* __restrict__ W1,
                                                 const float* __restrict__ b1) {
    __shared__ __align__(16) float sW[2 * IN_CH * D_MID];  // 14336 B
    __shared__ __align__(16) float sb[D_MID];
    for (int i = threadIdx.x; i < 2 * IN_CH * D_MID; i += blockDim.x) sW[i] = W1[i];
    for (int i = threadIdx.x; i < D_MID; i += blockDim.x) sb[i] = b1[i];
    __syncthreads();

    int n0 = blockIdx.x * 256 + threadIdx.x;
    int n[2] = {n0, n0 + 128};
    bool val[2];
#pragma unroll
    for (int i = 0; i < 2; i++) { val[i] = n[i] < N_NODES; if (!val[i]) n[i] = 0; }

    float xr[2][IN_CH];
#pragma unroll
    for (int i = 0; i < 2; i++) {
        const float4* xp = reinterpret_cast<const float4*>(x + n[i] * IN_CH);
#pragma unroll
        for (int c = 0; c < 8; c++) {
            float4 v = xp[c];
            xr[i][4 * c + 0] = v.x; xr[i][4 * c + 1] = v.y;
            xr[i][4 * c + 2] = v.z; xr[i][4 * c + 3] = v.w;
        }
    }

#pragma unroll
    for (int which = 0; which < 2; which++) {
        u64 h[2][D_MID / 2];
        if (which == 0) {
            const ulonglong2* bp = reinterpret_cast<const ulonglong2*>(sb);
#pragma unroll
            for (int j = 0; j < D_MID / 4; j++) {
                ulonglong2 v = bp[j];
#pragma unroll
                for (int i = 0; i < 2; i++) { h[i][2 * j] = v.x; h[i][2 * j + 1] = v.y; }
            }
        } else {
#pragma unroll
            for (int i = 0; i < 2; i++)
#pragma unroll
                for (int j = 0; j < D_MID / 2; j++) h[i][j] = 0ull;
        }
        const float* Wbase = sW + which * IN_CH * D_MID;
#pragma unroll
        for (int k = 0; k < IN_CH; k++) {
            u64 aa0 = pk2(xr[0][k], xr[0][k]);
            u64 aa1 = pk2(xr[1][k], xr[1][k]);
            const ulonglong2* w = reinterpret_cast<const ulonglong2*>(Wbase + k * D_MID);
#pragma unroll
            for (int j = 0; j < D_MID / 4; j++) {
                ulonglong2 ww = w[j];
                FMA2(h[0][2 * j],     aa0, ww.x, h[0][2 * j]);
                FMA2(h[0][2 * j + 1], aa0, ww.y, h[0][2 * j + 1]);
                FMA2(h[1][2 * j],     aa1, ww.x, h[1][2 * j]);
                FMA2(h[1][2 * j + 1], aa1, ww.y, h[1][2 * j + 1]);
            }
        }
        float* base = (which == 0 ? g_XR : g_XC);
#pragma unroll
        for (int i = 0; i < 2; i++) {
            if (!val[i]) continue;
            ulonglong2* dst = reinterpret_cast<ulonglong2*>(base + n[i] * D_MID);
#pragma unroll
            for (int j = 0; j < D_MID / 4; j++) {
                ulonglong2 v; v.x = h[i][2 * j]; v.y = h[i][2 * j + 1];
                dst[j] = v;
            }
        }
    }
}

// ---------------------------------------------------------------------------
// K2: per-edge MLP + scatter-max, 2 edges per thread
// ---------------------------------------------------------------------------
__device__ __forceinline__ void atomicMaxF(float* addr, float val) {
    if (val >= 0.0f) atomicMax(reinterpret_cast<int*>(addr), __float_as_int(val));
    else             atomicMin(reinterpret_cast<unsigned int*>(addr), __float_as_uint(val));
}

__global__ void __launch_bounds__(128, 2) k_edge(const int* __restrict__ idx32,
                                                 const float* __restrict__ edge_attr,
                                                 const float* __restrict__ W1,
                                                 const float* __restrict__ W2,
                                                 const float* __restrict__ b2,
                                                 float* __restrict__ out) {
    __shared__ __align__(16) float sWe[EDGE_CH * D_MID];  // W1 rows 64..79
    __shared__ __align__(16) float sW2[D_MID * OUT_CH];
    __shared__ __align__(16) float sb2[OUT_CH];

    const float* We = W1 + 2 * IN_CH * D_MID;
    for (int i = threadIdx.x; i < EDGE_CH * D_MID; i += blockDim.x) sWe[i] = We[i];
    for (int i = threadIdx.x; i < D_MID * OUT_CH; i += blockDim.x) sW2[i] = W2[i];
    for (int i = threadIdx.x; i < OUT_CH; i += blockDim.x) sb2[i] = b2[i];
    __syncthreads();

    int e0 = blockIdx.x * 256 + threadIdx.x;
    int e[2] = {e0, e0 + 128};
    bool val[2];
#pragma unroll
    for (int i = 0; i < 2; i++) { val[i] = e[i] < N_EDGES; if (!val[i]) e[i] = 0; }

    int rol[2], col[2];
    int is64 = g_is64;
#pragma unroll
    for (int i = 0; i < 2; i++) {
        if (is64) {
            rol[i] = idx32[2 * e[i]];
            col[i] = idx32[2 * (N_EDGES + e[i])];
        } else {
            rol[i] = idx32[e[i]];
            col[i] = idx32[N_EDGES + e[i]];
        }
    }
    const ulonglong2* pr[2] = {
        reinterpret_cast<const ulonglong2*>(g_XR + rol[0] * D_MID),
        reinterpret_cast<const ulonglong2*>(g_XR + rol[1] * D_MID)};
    const ulonglong2* pc[2] = {
        reinterpret_cast<const ulonglong2*>(g_XC + col[0] * D_MID),
        reinterpret_cast<const ulonglong2*>(g_XC + col[1] * D_MID)};

    // ---- layer 1a: h[i] = edge_attr[e_i] @ We  (gathers in flight behind this)
    float av[2][EDGE_CH];
#pragma unroll
    for (int i = 0; i < 2; i++) {
        const float4* pe = reinterpret_cast<const float4*>(edge_attr + e[i] * EDGE_CH);
#pragma unroll
        for (int c = 0; c < 4; c++) {
            float4 v = pe[c];
            av[i][4 * c + 0] = v.x; av[i][4 * c + 1] = v.y;
            av[i][4 * c + 2] = v.z; av[i][4 * c + 3] = v.w;
        }
    }
    u64 h[2][D_MID / 2];
#pragma unroll
    for (int k = 0; k < EDGE_CH; k++) {
        u64 aa0 = pk2(av[0][k], av[0][k]);
        u64 aa1 = pk2(av[1][k], av[1][k]);
        const ulonglong2* w = reinterpret_cast<const ulonglong2*>(&sWe[k * D_MID]);
#pragma unroll
        for (int j = 0; j < D_MID / 4; j++) {
            ulonglong2 ww = w[j];
            if (k == 0) {
                MUL2(h[0][2 * j],     aa0, ww.x);
                MUL2(h[0][2 * j + 1], aa0, ww.y);
                MUL2(h[1][2 * j],     aa1, ww.x);
                MUL2(h[1][2 * j + 1], aa1, ww.y);
            } else {
                FMA2(h[0][2 * j],     aa0, ww.x, h[0][2 * j]);
                FMA2(h[0][2 * j + 1], aa0, ww.y, h[0][2 * j + 1]);
                FMA2(h[1][2 * j],     aa1, ww.x, h[1][2 * j]);
                FMA2(h[1][2 * j + 1], aa1, ww.y, h[1][2 * j + 1]);
            }
        }
    }

    // ---- layer 1b: h[i] += XR[rol_i] + XC[col_i]
#pragma unroll
    for (int i = 0; i < 2; i++) {
#pragma unroll
        for (int j = 0; j < D_MID / 4; j++) {
            ulonglong2 a = pr[i][j];
            ulonglong2 b = pc[i][j];
            ADD2(h[i][2 * j],     h[i][2 * j],     a.x);
            ADD2(h[i][2 * j + 1], h[i][2 * j + 1], a.y);
            ADD2(h[i][2 * j],     h[i][2 * j],     b.x);
            ADD2(h[i][2 * j + 1], h[i][2 * j + 1], b.y);
        }
    }

    // ---- layer 2 fused with LeakyReLU; weight loads shared across both edges
    u64 o[2][OUT_CH / 2];
    {
        const ulonglong2* bp = reinterpret_cast<const ulonglong2*>(sb2);
#pragma unroll
        for (int j = 0; j < OUT_CH / 4; j++) {
            ulonglong2 v = bp[j];
#pragma unroll
            for (int i = 0; i < 2; i++) { o[i][2 * j] = v.x; o[i][2 * j + 1] = v.y; }
        }
    }
#pragma unroll
    for (int p = 0; p < D_MID / 2; p++) {
        float a0, b0, a1, b1v;
        upk2(a0, b0, h[0][p]);
        upk2(a1, b1v, h[1][p]);
        a0 = fmaxf(a0, 0.01f * a0);  b0 = fmaxf(b0, 0.01f * b0);
        a1 = fmaxf(a1, 0.01f * a1);  b1v = fmaxf(b1v, 0.01f * b1v);
        u64 aa0 = pk2(a0, a0), bb0 = pk2(b0, b0);
        u64 aa1 = pk2(a1, a1), bb1 = pk2(b1v, b1v);
        const ulonglong2* wa = reinterpret_cast<const ulonglong2*>(&sW2[(2 * p) * OUT_CH]);
        const ulonglong2* wb = reinterpret_cast<const ulonglong2*>(&sW2[(2 * p + 1) * OUT_CH]);
#pragma unroll
        for (int j = 0; j < OUT_CH / 4; j++) {
            ulonglong2 w0 = wa[j];
            FMA2(o[0][2 * j],     aa0, w0.x, o[0][2 * j]);
            FMA2(o[0][2 * j + 1], aa0, w0.y, o[0][2 * j + 1]);
            FMA2(o[1][2 * j],     aa1, w0.x, o[1][2 * j]);
            FMA2(o[1][2 * j + 1], aa1, w0.y, o[1][2 * j + 1]);
            ulonglong2 w1 = wb[j];
            FMA2(o[0][2 * j],     bb0, w1.x, o[0][2 * j]);
            FMA2(o[0][2 * j + 1], bb0, w1.y, o[0][2 * j + 1]);
            FMA2(o[1][2 * j],     bb1, w1.x, o[1][2 * j]);
            FMA2(o[1][2 * j + 1], bb1, w1.y, o[1][2 * j + 1]);
        }
    }

    // ---- LeakyReLU + filtered scatter-max ----
#pragma unroll
    for (int i = 0; i < 2; i++) {
        if (!val[i]) continue;
        float* orow = out + col[i] * OUT_CH;
        const float4* oro = reinterpret_cast<const float4*>(orow);
#pragma unroll
        for (int q = 0; q < OUT_CH / 4; q++) {
            float v0, v1, v2, v3;
            upk2(v0, v1, o[i][2 * q]);
            upk2(v2, v3, o[i][2 * q + 1]);
            v0 = fmaxf(v0, 0.01f * v0);
            v1 = fmaxf(v1, 0.01f * v1);
            v2 = fmaxf(v2, 0.01f * v2);
            v3 = fmaxf(v3, 0.01f * v3);
            float4 cur = oro[q];                 // monotone max: stale read is safe
            if (v0 > cur.x) atomicMaxF(orow + 4 * q + 0, v0);
            if (v1 > cur.y) atomicMaxF(orow + 4 * q + 1, v1);
            if (v2 > cur.z) atomicMaxF(orow + 4 * q + 2, v2);
            if (v3 > cur.w) atomicMaxF(orow + 4 * q + 3, v3);
        }
    }
}

// ---------------------------------------------------------------------------
// K3: finalize — -inf -> 0, elementwise max with x
// ---------------------------------------------------------------------------
__global__ void k_final(const float* __restrict__ x, float* __restrict__ out) {
    int i = blockIdx.x * blockDim.x + threadIdx.x;
    if (i >= N_NODES * OUT_CH) return;
    float a = out[i];
    if (__float_as_uint(a) == 0xFF800000u) a = 0.0f;
    out[i] = fmaxf(a, x[i]);
}

// ---------------------------------------------------------------------------
extern "C" void kernel_launch(void* const* d_in, const int* in_sizes, int n_in,
                              void* d_out, int out_size) {
    const float* x         = (const float*)d_in[0];
    const int*   idx32     = (const int*)d_in[1];
    const float* edge_attr = (const float*)d_in[2];
    const float* W1        = (const float*)d_in[3];
    const float* b1        = (const float*)d_in[4];
    const float* W2        = (const float*)d_in[5];
    const float* b2        = (const float*)d_in[6];
    float* out = (float*)d_out;

    k_pre<<<592, 256>>>((const unsigned int*)d_in[1], (unsigned int*)d_out);
    k_node<<<(N_NODES + 255) / 256, 128>>>(x, W1, b1);
    k_edge<<<(N_EDGES + 255) / 256, 128>>>(idx32, edge_attr, W1, W2, b2, out);
    k_final<<<(N_NODES * OUT_CH + 255) / 256, 256>>>(x, out);
}

// round 5
// speedup vs baseline: 1.0597x; 1.0597x over previous
#include <cuda_runtime.h>
#include <cstdint>

#define N_NODES 100000
#define N_EDGES 1000000
#define IN_CH   32
#define EDGE_CH 16
#define OUT_CH  32
#define D_MID   56
#define ROW_PAD 60   // 56 floats padded to 60 (240B, 16B-aligned stride)

typedef unsigned long long u64;

static __device__ int   g_is64;
static __device__ __align__(16) float g_XR[N_NODES * D_MID];  // x @ W1[0:32]  + b1
static __device__ __align__(16) float g_XC[N_NODES * D_MID];  // x @ W1[32:64]

// ---- packed f32x2 helpers ---------------------------------------------------
__device__ __forceinline__ u64 pk2(float a, float b) {
    u64 r; asm("mov.b64 %0, {%1,%2};" : "=l"(r) : "f"(a), "f"(b)); return r;
}
__device__ __forceinline__ void upk2(float& a, float& b, u64 v) {
    asm("mov.b64 {%0,%1}, %2;" : "=f"(a), "=f"(b) : "l"(v));
}
#define FMA2(d, a, b, c) asm("fma.rn.f32x2 %0, %1, %2, %3;" : "=l"(d) : "l"(a), "l"(b), "l"(c))
#define MUL2(d, a, b)    asm("mul.rn.f32x2 %0, %1, %2;"     : "=l"(d) : "l"(a), "l"(b))
#define ADD2(d, a, b)    asm("add.rn.f32x2 %0, %1, %2;"     : "=l"(d) : "l"(a), "l"(b))

// ---------------------------------------------------------------------------
// K0: init output to -inf + (block 0) detect int64 vs int32 edge_index
// ---------------------------------------------------------------------------
__global__ void k_pre(const unsigned int* __restrict__ w, unsigned int* __restrict__ out) {
    if (blockIdx.x == 0) {
        __shared__ int bad;
        if (threadIdx.x == 0) bad = 0;
        __syncthreads();
        for (int i = threadIdx.x; i < 4096; i += blockDim.x)
            if (w[2 * i + 1] != 0u) bad = 1;   // benign race
        __syncthreads();
        if (threadIdx.x == 0) g_is64 = !bad;
    }
    int stride = gridDim.x * blockDim.x;
    for (int i = blockIdx.x * blockDim.x + threadIdx.x; i < N_NODES * OUT_CH; i += stride)
        out[i] = 0xFF800000u;  // -inf
}

// ---------------------------------------------------------------------------
// K1: fused per-node precompute: XR = x@W1[0:32]+b1 and XC = x@W1[32:64]
// ---------------------------------------------------------------------------
__global__ void __launch_bounds__(128) k_node(const float* __restrict__ x,
                                              const float* __restrict__ W1,
                                              const float* __restrict__ b1) {
    __shared__ __align__(16) float sW[2 * IN_CH * D_MID];  // 14336 B
    __shared__ __align__(16) float sb[D_MID];
    for (int i = threadIdx.x; i < 2 * IN_CH * D_MID; i += blockDim.x) sW[i] = W1[i];
    for (int i = threadIdx.x; i < D_MID; i += blockDim.x) sb[i] = b1[i];
    __syncthreads();

    int n = blockIdx.x * blockDim.x + threadIdx.x;
    if (n >= N_NODES) return;

    float xr[IN_CH];
    const float4* xp = reinterpret_cast<const float4*>(x + n * IN_CH);
#pragma unroll
    for (int c = 0; c < 8; c++) {
        float4 v = xp[c];
        xr[4 * c + 0] = v.x; xr[4 * c + 1] = v.y; xr[4 * c + 2] = v.z; xr[4 * c + 3] = v.w;
    }

#pragma unroll
    for (int which = 0; which < 2; which++) {
        u64 h[D_MID / 2];
        if (which == 0) {
            const ulonglong2* bp = reinterpret_cast<const ulonglong2*>(sb);
#pragma unroll
            for (int j = 0; j < D_MID / 4; j++) {
                ulonglong2 v = bp[j];
                h[2 * j] = v.x; h[2 * j + 1] = v.y;
            }
        } else {
#pragma unroll
            for (int j = 0; j < D_MID / 2; j++) h[j] = 0ull;
        }
        const float* Wbase = sW + which * IN_CH * D_MID;
#pragma unroll
        for (int k = 0; k < IN_CH; k++) {
            u64 aa = pk2(xr[k], xr[k]);
            const ulonglong2* w = reinterpret_cast<const ulonglong2*>(Wbase + k * D_MID);
#pragma unroll
            for (int j = 0; j < D_MID / 4; j++) {
                ulonglong2 ww = w[j];
                FMA2(h[2 * j],     aa, ww.x, h[2 * j]);
                FMA2(h[2 * j + 1], aa, ww.y, h[2 * j + 1]);
            }
        }
        ulonglong2* dst = reinterpret_cast<ulonglong2*>((which == 0 ? g_XR : g_XC) + n * D_MID);
#pragma unroll
        for (int j = 0; j < D_MID / 4; j++) {
            ulonglong2 v; v.x = h[2 * j]; v.y = h[2 * j + 1];
            dst[j] = v;
        }
    }
}

// ---------------------------------------------------------------------------
// K2: per-edge MLP + scatter-max, warp-cooperative gather staging
// ---------------------------------------------------------------------------
__device__ __forceinline__ void atomicMaxF(float* addr, float val) {
    if (val >= 0.0f) atomicMax(reinterpret_cast<int*>(addr), __float_as_int(val));
    else             atomicMin(reinterpret_cast<unsigned int*>(addr), __float_as_uint(val));
}

// Cooperatively stage 32 rows (one per lane, index in `row` of each lane) of a
// 56-float table into the warp's smem buffer. 2 rows per iteration:
// lanes 0-13 load row r2, lanes 16-29 load row r2+1.
__device__ __forceinline__ void stage_rows(const float* __restrict__ table,
                                           int row, float* __restrict__ sb,
                                           int half, int sub) {
#pragma unroll
    for (int r2 = 0; r2 < 32; r2 += 2) {
        int src0 = __shfl_sync(0xffffffffu, row, r2);
        int src1 = __shfl_sync(0xffffffffu, row, r2 + 1);
        int src  = half ? src1 : src0;
        int r    = r2 + half;
        if (sub < 14) {
            float4 v = __ldg(reinterpret_cast<const float4*>(table + (size_t)src * D_MID) + sub);
            *reinterpret_cast<float4*>(sb + r * ROW_PAD + sub * 4) = v;
        }
    }
}

__global__ void __launch_bounds__(128) k_edge(const int* __restrict__ idx32,
                                              const float* __restrict__ edge_attr,
                                              const float* __restrict__ W1,
                                              const float* __restrict__ W2,
                                              const float* __restrict__ b2,
                                              float* __restrict__ out) {
    __shared__ __align__(16) float sWe[EDGE_CH * D_MID];   // 3584 B
    __shared__ __align__(16) float sW2[D_MID * OUT_CH];    // 7168 B
    __shared__ __align__(16) float sb2[OUT_CH];
    __shared__ __align__(16) float sbuf[4][32 * ROW_PAD];  // 4 x 7680 B

    const float* We = W1 + 2 * IN_CH * D_MID;
    for (int i = threadIdx.x; i < EDGE_CH * D_MID; i += blockDim.x) sWe[i] = We[i];
    for (int i = threadIdx.x; i < D_MID * OUT_CH; i += blockDim.x) sW2[i] = W2[i];
    for (int i = threadIdx.x; i < OUT_CH; i += blockDim.x) sb2[i] = b2[i];
    __syncthreads();

    const int warp = threadIdx.x >> 5;
    const int lane = threadIdx.x & 31;
    const int half = lane >> 4;
    const int sub  = lane & 15;
    float* sb = sbuf[warp];

    int e = blockIdx.x * 128 + warp * 32 + lane;
    bool valid = e < N_EDGES;
    int ec = valid ? e : N_EDGES - 1;

    int rol, col;
    if (g_is64) {
        rol = idx32[2 * ec];
        col = idx32[2 * (N_EDGES + ec)];
    } else {
        rol = idx32[ec];
        col = idx32[N_EDGES + ec];
    }

    // ---- stage XR rows (LDG latency overlapped by layer-1a FMAs below) ----
    stage_rows(g_XR, rol, sb, half, sub);

    // ---- layer 1a: h = edge_attr[ec] @ We (smem-only compute) ----
    u64 h[D_MID / 2];
    {
        const float4* pe = reinterpret_cast<const float4*>(edge_attr + ec * EDGE_CH);
        float av[EDGE_CH];
#pragma unroll
        for (int c = 0; c < 4; c++) {
            float4 v = pe[c];
            av[4 * c + 0] = v.x; av[4 * c + 1] = v.y; av[4 * c + 2] = v.z; av[4 * c + 3] = v.w;
        }
#pragma unroll
        for (int k = 0; k < EDGE_CH; k++) {
            u64 aa = pk2(av[k], av[k]);
            const ulonglong2* w = reinterpret_cast<const ulonglong2*>(&sWe[k * D_MID]);
#pragma unroll
            for (int j = 0; j < D_MID / 4; j++) {
                ulonglong2 ww = w[j];
                if (k == 0) {
                    MUL2(h[2 * j],     aa, ww.x);
                    MUL2(h[2 * j + 1], aa, ww.y);
                } else {
                    FMA2(h[2 * j],     aa, ww.x, h[2 * j]);
                    FMA2(h[2 * j + 1], aa, ww.y, h[2 * j + 1]);
                }
            }
        }
    }

    // ---- consume XR row from smem ----
    __syncwarp();
    {
        const ulonglong2* pr = reinterpret_cast<const ulonglong2*>(sb + lane * ROW_PAD);
#pragma unroll
        for (int j = 0; j < D_MID / 4; j++) {
            ulonglong2 a = pr[j];
            ADD2(h[2 * j],     h[2 * j],     a.x);
            ADD2(h[2 * j + 1], h[2 * j + 1], a.y);
        }
    }
    __syncwarp();

    // ---- stage + consume XC rows ----
    stage_rows(g_XC, col, sb, half, sub);
    __syncwarp();
    {
        const ulonglong2* pc = reinterpret_cast<const ulonglong2*>(sb + lane * ROW_PAD);
#pragma unroll
        for (int j = 0; j < D_MID / 4; j++) {
            ulonglong2 a = pc[j];
            ADD2(h[2 * j],     h[2 * j],     a.x);
            ADD2(h[2 * j + 1], h[2 * j + 1], a.y);
        }
    }

    // ---- layer 2 fused with LeakyReLU, iterating over h pairs (h dies early)
    u64 o[OUT_CH / 2];
    {
        const ulonglong2* bp = reinterpret_cast<const ulonglong2*>(sb2);
#pragma unroll
        for (int j = 0; j < OUT_CH / 4; j++) {
            ulonglong2 v = bp[j];
            o[2 * j] = v.x; o[2 * j + 1] = v.y;
        }
    }
#pragma unroll
    for (int p = 0; p < D_MID / 2; p++) {
        float a, b; upk2(a, b, h[p]);
        a = fmaxf(a, 0.01f * a);
        b = fmaxf(b, 0.01f * b);
        u64 aa = pk2(a, a);
        u64 bb = pk2(b, b);
        const ulonglong2* wa = reinterpret_cast<const ulonglong2*>(&sW2[(2 * p) * OUT_CH]);
        const ulonglong2* wb = reinterpret_cast<const ulonglong2*>(&sW2[(2 * p + 1) * OUT_CH]);
#pragma unroll
        for (int j = 0; j < OUT_CH / 4; j++) {
            ulonglong2 w0 = wa[j];
            FMA2(o[2 * j],     aa, w0.x, o[2 * j]);
            FMA2(o[2 * j + 1], aa, w0.y, o[2 * j + 1]);
            ulonglong2 w1 = wb[j];
            FMA2(o[2 * j],     bb, w1.x, o[2 * j]);
            FMA2(o[2 * j + 1], bb, w1.y, o[2 * j + 1]);
        }
    }

    // ---- LeakyReLU + filtered scatter-max ----
    if (valid) {
        float* orow = out + col * OUT_CH;
        const float4* oro = reinterpret_cast<const float4*>(orow);
#pragma unroll
        for (int q = 0; q < OUT_CH / 4; q++) {
            float v0, v1, v2, v3;
            upk2(v0, v1, o[2 * q]);
            upk2(v2, v3, o[2 * q + 1]);
            v0 = fmaxf(v0, 0.01f * v0);
            v1 = fmaxf(v1, 0.01f * v1);
            v2 = fmaxf(v2, 0.01f * v2);
            v3 = fmaxf(v3, 0.01f * v3);
            float4 cur = oro[q];                 // monotone max: stale read is safe
            if (v0 > cur.x) atomicMaxF(orow + 4 * q + 0, v0);
            if (v1 > cur.y) atomicMaxF(orow + 4 * q + 1, v1);
            if (v2 > cur.z) atomicMaxF(orow + 4 * q + 2, v2);
            if (v3 > cur.w) atomicMaxF(orow + 4 * q + 3, v3);
        }
    }
}

// ---------------------------------------------------------------------------
// K3: finalize — -inf -> 0, elementwise max with x
// ---------------------------------------------------------------------------
__global__ void k_final(const float* __restrict__ x, float* __restrict__ out) {
    int i = blockIdx.x * blockDim.x + threadIdx.x;
    if (i >= N_NODES * OUT_CH) return;
    float a = out[i];
    if (__float_as_uint(a) == 0xFF800000u) a = 0.0f;
    out[i] = fmaxf(a, x[i]);
}

// ---------------------------------------------------------------------------
extern "C" void kernel_launch(void* const* d_in, const int* in_sizes, int n_in,
                              void* d_out, int out_size) {
    const float* x         = (const float*)d_in[0];
    const int*   idx32     = (const int*)d_in[1];
    const float* edge_attr = (const float*)d_in[2];
    const float* W1        = (const float*)d_in[3];
    const float* b1        = (const float*)d_in[4];
    const float* W2        = (const float*)d_in[5];
    const float* b2        = (const float*)d_in[6];
    float* out = (float*)d_out;

    k_pre<<<592, 256>>>((const unsigned int*)d_in[1], (unsigned int*)d_out);
    k_node<<<(N_NODES + 127) / 128, 128>>>(x, W1, b1);
    k_edge<<<(N_EDGES + 127) / 128, 128>>>(idx32, edge_attr, W1, W2, b2, out);
    k_final<<<(N_NODES * OUT_CH + 255) / 256, 256>>>(x, out);
}

// round 6
// speedup vs baseline: 1.1103x; 1.0478x over previous
#include <cuda_runtime.h>
#include <cstdint>

#define N_NODES 100000
#define N_EDGES 1000000
#define IN_CH   32
#define EDGE_CH 16
#define OUT_CH  32
#define D_MID   56
#define EA_PAD  17   // edge_attr smem row stride (conflict-free: 17 coprime 32)

typedef unsigned long long u64;

static __device__ int   g_is64;
static __device__ __align__(16) float g_XR[N_NODES * D_MID];  // x @ W1[0:32]  + b1
static __device__ __align__(16) float g_XC[N_NODES * D_MID];  // x @ W1[32:64]

// ---- packed f32x2 helpers ---------------------------------------------------
__device__ __forceinline__ u64 pk2(float a, float b) {
    u64 r; asm("mov.b64 %0, {%1,%2};" : "=l"(r) : "f"(a), "f"(b)); return r;
}
__device__ __forceinline__ void upk2(float& a, float& b, u64 v) {
    asm("mov.b64 {%0,%1}, %2;" : "=f"(a), "=f"(b) : "l"(v));
}
#define FMA2(d, a, b, c) asm("fma.rn.f32x2 %0, %1, %2, %3;" : "=l"(d) : "l"(a), "l"(b), "l"(c))
#define MUL2(d, a, b)    asm("mul.rn.f32x2 %0, %1, %2;"     : "=l"(d) : "l"(a), "l"(b))
#define ADD2(d, a, b)    asm("add.rn.f32x2 %0, %1, %2;"     : "=l"(d) : "l"(a), "l"(b))

// ---------------------------------------------------------------------------
// K0: init output to -inf + (block 0) detect int64 vs int32 edge_index
// ---------------------------------------------------------------------------
__global__ void k_pre(const unsigned int* __restrict__ w, unsigned int* __restrict__ out) {
    if (blockIdx.x == 0) {
        __shared__ int bad;
        if (threadIdx.x == 0) bad = 0;
        __syncthreads();
        for (int i = threadIdx.x; i < 4096; i += blockDim.x)
            if (w[2 * i + 1] != 0u) bad = 1;   // benign race
        __syncthreads();
        if (threadIdx.x == 0) g_is64 = !bad;
    }
    int stride = gridDim.x * blockDim.x;
    for (int i = blockIdx.x * blockDim.x + threadIdx.x; i < N_NODES * OUT_CH; i += stride)
        out[i] = 0xFF800000u;  // -inf
}

// ---------------------------------------------------------------------------
// K1: per-node precompute, j-blocked (low regs -> high occupancy)
// ---------------------------------------------------------------------------
__global__ void __launch_bounds__(128, 8) k_node(const float* __restrict__ x,
                                                 const float* __restrict__ W1,
                                                 const float* __restrict__ b1) {
    __shared__ __align__(16) float sW[2 * IN_CH * D_MID];  // 14336 B
    __shared__ __align__(16) float sb[D_MID];
    for (int i = threadIdx.x; i < 2 * IN_CH * D_MID; i += blockDim.x) sW[i] = W1[i];
    for (int i = threadIdx.x; i < D_MID; i += blockDim.x) sb[i] = b1[i];
    __syncthreads();

    int n = blockIdx.x * blockDim.x + threadIdx.x;
    if (n >= N_NODES) return;

    float xr[IN_CH];
    const float4* xp = reinterpret_cast<const float4*>(x + n * IN_CH);
#pragma unroll
    for (int c = 0; c < 8; c++) {
        float4 v = xp[c];
        xr[4 * c + 0] = v.x; xr[4 * c + 1] = v.y; xr[4 * c + 2] = v.z; xr[4 * c + 3] = v.w;
    }

#pragma unroll
    for (int which = 0; which < 2; which++) {
        float* dstbase = (which == 0 ? g_XR : g_XC) + (size_t)n * D_MID;
        const float* Wbase = sW + which * IN_CH * D_MID;
#pragma unroll
        for (int jb = 0; jb < D_MID / 8; jb++) {
            u64 hb0, hb1, hb2, hb3;
            if (which == 0) {
                const ulonglong2* bp = reinterpret_cast<const ulonglong2*>(&sb[8 * jb]);
                ulonglong2 b01 = bp[0], b23 = bp[1];
                hb0 = b01.x; hb1 = b01.y; hb2 = b23.x; hb3 = b23.y;
            } else {
                hb0 = hb1 = hb2 = hb3 = 0ull;
            }
#pragma unroll
            for (int k = 0; k < IN_CH; k++) {
                u64 aa = pk2(xr[k], xr[k]);
                const ulonglong2* w = reinterpret_cast<const ulonglong2*>(Wbase + k * D_MID + 8 * jb);
                ulonglong2 w0 = w[0], w1 = w[1];
                FMA2(hb0, aa, w0.x, hb0);
                FMA2(hb1, aa, w0.y, hb1);
                FMA2(hb2, aa, w1.x, hb2);
                FMA2(hb3, aa, w1.y, hb3);
            }
            ulonglong2* dst = reinterpret_cast<ulonglong2*>(dstbase + 8 * jb);
            ulonglong2 s0; s0.x = hb0; s0.y = hb1;
            ulonglong2 s1; s1.x = hb2; s1.y = hb3;
            dst[0] = s0; dst[1] = s1;
        }
    }
}

// ---------------------------------------------------------------------------
// K2: per-edge MLP + scatter-max, j-blocked (h never fully live)
// ---------------------------------------------------------------------------
__device__ __forceinline__ void atomicMaxF(float* addr, float val) {
    if (val >= 0.0f) atomicMax(reinterpret_cast<int*>(addr), __float_as_int(val));
    else             atomicMin(reinterpret_cast<unsigned int*>(addr), __float_as_uint(val));
}

__global__ void __launch_bounds__(128, 6) k_edge(const int* __restrict__ idx32,
                                                 const float* __restrict__ edge_attr,
                                                 const float* __restrict__ W1,
                                                 const float* __restrict__ W2,
                                                 const float* __restrict__ b2,
                                                 float* __restrict__ out) {
    __shared__ __align__(16) float sWe[EDGE_CH * D_MID];   // 3584 B
    __shared__ __align__(16) float sW2[D_MID * OUT_CH];    // 7168 B
    __shared__ __align__(16) float sb2[OUT_CH];
    __shared__ float sea[128 * EA_PAD];                    // 8704 B

    const float* We = W1 + 2 * IN_CH * D_MID;
    for (int i = threadIdx.x; i < EDGE_CH * D_MID; i += blockDim.x) sWe[i] = We[i];
    for (int i = threadIdx.x; i < D_MID * OUT_CH; i += blockDim.x) sW2[i] = W2[i];
    for (int i = threadIdx.x; i < OUT_CH; i += blockDim.x) sb2[i] = b2[i];

    // stage this block's edge_attr tile (coalesced -> padded rows)
    int base = blockIdx.x * 128;
#pragma unroll
    for (int i = 0; i < 16; i++) {
        int local = threadIdx.x + 128 * i;
        int gidx  = base * EDGE_CH + local;
        float v = 0.0f;
        if (gidx < N_EDGES * EDGE_CH) v = edge_attr[gidx];
        sea[(local >> 4) * EA_PAD + (local & 15)] = v;
    }
    __syncthreads();

    int e = base + threadIdx.x;
    bool valid = e < N_EDGES;
    int ec = valid ? e : N_EDGES - 1;

    int rol, col;
    if (g_is64) {
        rol = idx32[2 * ec];
        col = idx32[2 * (N_EDGES + ec)];
    } else {
        rol = idx32[ec];
        col = idx32[N_EDGES + ec];
    }
    const ulonglong2* pr = reinterpret_cast<const ulonglong2*>(g_XR + (size_t)rol * D_MID);
    const ulonglong2* pc = reinterpret_cast<const ulonglong2*>(g_XC + (size_t)col * D_MID);
    const float* myea = &sea[threadIdx.x * EA_PAD];

    // persistent layer-2 accumulators
    u64 o[OUT_CH / 2];
    {
        const ulonglong2* bp = reinterpret_cast<const ulonglong2*>(sb2);
#pragma unroll
        for (int j = 0; j < OUT_CH / 4; j++) {
            ulonglong2 v = bp[j];
            o[2 * j] = v.x; o[2 * j + 1] = v.y;
        }
    }

#pragma unroll
    for (int jb = 0; jb < D_MID / 8; jb++) {
        // gathers for this 8-wide chunk (in flight behind the FMA block below)
        ulonglong2 r0 = pr[2 * jb], r1 = pr[2 * jb + 1];
        ulonglong2 c0 = pc[2 * jb], c1 = pc[2 * jb + 1];

        // layer 1a for this chunk: h[8jb..8jb+7] = edge_attr @ We[:, chunk]
        u64 hb0, hb1, hb2, hb3;
#pragma unroll
        for (int k = 0; k < EDGE_CH; k++) {
            float a = myea[k];
            u64 aa = pk2(a, a);
            const ulonglong2* w = reinterpret_cast<const ulonglong2*>(&sWe[k * D_MID + 8 * jb]);
            ulonglong2 w0 = w[0], w1 = w[1];
            if (k == 0) {
                MUL2(hb0, aa, w0.x);
                MUL2(hb1, aa, w0.y);
                MUL2(hb2, aa, w1.x);
                MUL2(hb3, aa, w1.y);
            } else {
                FMA2(hb0, aa, w0.x, hb0);
                FMA2(hb1, aa, w0.y, hb1);
                FMA2(hb2, aa, w1.x, hb2);
                FMA2(hb3, aa, w1.y, hb3);
            }
        }
        // add gathered XR + XC contributions
        ADD2(hb0, hb0, r0.x); ADD2(hb1, hb1, r0.y);
        ADD2(hb2, hb2, r1.x); ADD2(hb3, hb3, r1.y);
        ADD2(hb0, hb0, c0.x); ADD2(hb1, hb1, c0.y);
        ADD2(hb2, hb2, c1.x); ADD2(hb3, hb3, c1.y);

        // LeakyReLU + accumulate into o (h chunk dies here)
        u64 hbs[4] = {hb0, hb1, hb2, hb3};
#pragma unroll
        for (int p = 0; p < 4; p++) {
            float a, b; upk2(a, b, hbs[p]);
            a = fmaxf(a, 0.01f * a);
            b = fmaxf(b, 0.01f * b);
            u64 aa = pk2(a, a);
            u64 bb = pk2(b, b);
            const ulonglong2* wa = reinterpret_cast<const ulonglong2*>(&sW2[(8 * jb + 2 * p) * OUT_CH]);
            const ulonglong2* wb = reinterpret_cast<const ulonglong2*>(&sW2[(8 * jb + 2 * p + 1) * OUT_CH]);
#pragma unroll
            for (int j = 0; j < OUT_CH / 4; j++) {
                ulonglong2 w0 = wa[j];
                FMA2(o[2 * j],     aa, w0.x, o[2 * j]);
                FMA2(o[2 * j + 1], aa, w0.y, o[2 * j + 1]);
                ulonglong2 w1 = wb[j];
                FMA2(o[2 * j],     bb, w1.x, o[2 * j]);
                FMA2(o[2 * j + 1], bb, w1.y, o[2 * j + 1]);
            }
        }
    }

    // ---- LeakyReLU + filtered scatter-max ----
    if (valid) {
        float* orow = out + col * OUT_CH;
        const float4* oro = reinterpret_cast<const float4*>(orow);
#pragma unroll
        for (int q = 0; q < OUT_CH / 4; q++) {
            float v0, v1, v2, v3;
            upk2(v0, v1, o[2 * q]);
            upk2(v2, v3, o[2 * q + 1]);
            v0 = fmaxf(v0, 0.01f * v0);
            v1 = fmaxf(v1, 0.01f * v1);
            v2 = fmaxf(v2, 0.01f * v2);
            v3 = fmaxf(v3, 0.01f * v3);
            float4 cur = oro[q];                 // monotone max: stale read is safe
            if (v0 > cur.x) atomicMaxF(orow + 4 * q + 0, v0);
            if (v1 > cur.y) atomicMaxF(orow + 4 * q + 1, v1);
            if (v2 > cur.z) atomicMaxF(orow + 4 * q + 2, v2);
            if (v3 > cur.w) atomicMaxF(orow + 4 * q + 3, v3);
        }
    }
}

// ---------------------------------------------------------------------------
// K3: finalize — -inf -> 0, elementwise max with x
// ---------------------------------------------------------------------------
__global__ void k_final(const float* __restrict__ x, float* __restrict__ out) {
    int i = blockIdx.x * blockDim.x + threadIdx.x;
    if (i >= N_NODES * OUT_CH) return;
    float a = out[i];
    if (__float_as_uint(a) == 0xFF800000u) a = 0.0f;
    out[i] = fmaxf(a, x[i]);
}

// ---------------------------------------------------------------------------
extern "C" void kernel_launch(void* const* d_in, const int* in_sizes, int n_in,
                              void* d_out, int out_size) {
    const float* x         = (const float*)d_in[0];
    const int*   idx32     = (const int*)d_in[1];
    const float* edge_attr = (const float*)d_in[2];
    const float* W1        = (const float*)d_in[3];
    const float* b1        = (const float*)d_in[4];
    const float* W2        = (const float*)d_in[5];
    const float* b2        = (const float*)d_in[6];
    float* out = (float*)d_out;

    k_pre<<<592, 256>>>((const unsigned int*)d_in[1], (unsigned int*)d_out);
    k_node<<<(N_NODES + 127) / 128, 128>>>(x, W1, b1);
    k_edge<<<(N_EDGES + 127) / 128, 128>>>(idx32, edge_attr, W1, W2, b2, out);
    k_final<<<(N_NODES * OUT_CH + 255) / 256, 256>>>(x, out);
}